// round 4
// baseline (speedup 1.0000x reference)
#include <cuda_runtime.h>
#include <math.h>

#define B_    2048
#define K_    20
#define TK_   40
#define D_    128
#define T_    100
#define C_    128
#define HT_   20
#define HC_   512
#define F1_   228   /* D+T  */
#define F2_   484   /* 3D+T */

typedef unsigned long long u64;

// ---------------- scratch (no allocations allowed) ----------------
__device__ float g_tok1[B_ * TK_ * C_];
__device__ float g_tok2[B_ * TK_ * C_];

__device__ __forceinline__ float gelu_f(float x) {
    return 0.5f * x * (1.0f + erff(x * 0.70710678118654752f));
}
__device__ __forceinline__ u64 pk2(float lo, float hi) {
    u64 r; asm("mov.b64 %0, {%1,%2};" : "=l"(r) : "f"(lo), "f"(hi)); return r;
}
__device__ __forceinline__ u64 fma2(u64 a, u64 b, u64 c) {
    u64 d; asm("fma.rn.f32x2 %0, %1, %2, %3;" : "=l"(d) : "l"(a), "l"(b), "l"(c)); return d;
}
__device__ __forceinline__ float2 up2(u64 a) {
    float2 f; asm("mov.b64 {%0,%1}, %2;" : "=f"(f.x), "=f"(f.y) : "l"(a)); return f;
}

// ================= one-hop build: gather + time-enc + proj (f32x2) =================
// 128 threads: cq = tid&31 -> channels 4cq..4cq+3 (2 pairs); tg = tid>>5 -> tokens tg*10..+9
#define FD1_  230   /* u64 stride (even) */
__global__ __launch_bounds__(128)
void k_build1(const float* __restrict__ et, const int* __restrict__ se,
              const int* __restrict__ de, const float* __restrict__ dts,
              const float* __restrict__ dtd, const float* __restrict__ tw,
              const float* __restrict__ tb, const float* __restrict__ pW,
              const float* __restrict__ pb, float* __restrict__ out)
{
    extern __shared__ u64 fd[];            // [TK_][FD1_] duplicated features
    __shared__ int   s_eid[TK_];
    __shared__ float s_dt[TK_];
    int b = blockIdx.x, tid = threadIdx.x;
    if (tid < TK_) {
        int half = tid / K_, k = tid - half * K_;
        int eid = half ? de[b * K_ + k] : se[b * K_ + k];
        s_eid[tid] = eid;
        s_dt[tid]  = half ? dtd[b * K_ + k] : dts[b * K_ + k];
    }
    __syncthreads();
    for (int idx = tid; idx < TK_ * F1_; idx += 128) {
        int t = idx / F1_, f = idx - t * F1_;
        float v;
        if (f < D_) v = et[(long)s_eid[t] * D_ + f];
        else {
            int j = f - D_;
            v = (s_eid[t] == 0) ? 0.0f : cosf(s_dt[t] * tw[j] + tb[j]);
        }
        fd[t * FD1_ + f] = pk2(v, v);
    }
    __syncthreads();

    int cq = tid & 31, tg = tid >> 5;
    int c0 = cq * 4, t0 = tg * 10;
    u64 acc[10][2];
#pragma unroll
    for (int t = 0; t < 10; t++) { acc[t][0] = 0ull; acc[t][1] = 0ull; }

#pragma unroll 4
    for (int k = 0; k < F1_; k += 2) {
        ulonglong2 w0 = *(const ulonglong2*)(pW + (long)k * C_ + c0);
        ulonglong2 w1 = *(const ulonglong2*)(pW + (long)(k + 1) * C_ + c0);
#pragma unroll
        for (int t = 0; t < 10; t++) {
            ulonglong2 xd = *(const ulonglong2*)(fd + (t0 + t) * FD1_ + k);
            acc[t][0] = fma2(w0.x, xd.x, acc[t][0]);
            acc[t][1] = fma2(w0.y, xd.x, acc[t][1]);
            acc[t][0] = fma2(w1.x, xd.y, acc[t][0]);
            acc[t][1] = fma2(w1.y, xd.y, acc[t][1]);
        }
    }
    float4 bias = *(const float4*)(pb + c0);
#pragma unroll
    for (int t = 0; t < 10; t++) {
        float2 p0 = up2(acc[t][0]), p1 = up2(acc[t][1]);
        float4 o;
        o.x = p0.x + bias.x; o.y = p0.y + bias.y;
        o.z = p1.x + bias.z; o.w = p1.y + bias.w;
        *(float4*)(out + ((long)b * TK_ + t0 + t) * C_ + c0) = o;
    }
}

// ================= two-hop build (f32x2) =================
#define FD2_  486   /* u64 stride (even) */
__global__ __launch_bounds__(128)
void k_build2(const float* __restrict__ et, const int* __restrict__ se,
              const int* __restrict__ de, const int* __restrict__ s2a,
              const int* __restrict__ s2b, const int* __restrict__ d2a,
              const int* __restrict__ d2b, const float* __restrict__ dt2s,
              const float* __restrict__ dt2d, const float* __restrict__ tw,
              const float* __restrict__ tb, const float* __restrict__ eW,
              const float* __restrict__ eb, float* __restrict__ out)
{
    extern __shared__ u64 fd2[];           // [K_][FD2_]
    __shared__ int s1[K_], s2[K_], s3[K_];
    __shared__ float sdt[K_];
    int bh = blockIdx.x;
    int b = bh >> 1, half = bh & 1, tid = threadIdx.x;
    if (tid < K_) {
        s1[tid] = half ? d2a[b * K_ + tid] : s2a[b * K_ + tid];
        s2[tid] = half ? d2b[b * K_ + tid] : s2b[b * K_ + tid];
        s3[tid] = half ? de[b * K_ + tid]  : se[b * K_ + tid];
        sdt[tid] = half ? dt2d[b * K_ + tid] : dt2s[b * K_ + tid];
    }
    __syncthreads();
    for (int idx = tid; idx < K_ * F2_; idx += 128) {
        int t = idx / F2_, f = idx - t * F2_;
        float v;
        if (f < D_)              v = et[(long)s1[t] * D_ + f];
        else if (f < 2 * D_)     v = et[(long)s2[t] * D_ + (f - D_)];
        else if (f < 3 * D_)     v = et[(long)s3[t] * D_ + (f - 2 * D_)];
        else {
            int j = f - 3 * D_;
            v = (s1[t] == 0) ? 0.0f : cosf(sdt[t] * tw[j] + tb[j]);
        }
        fd2[t * FD2_ + f] = pk2(v, v);
    }
    __syncthreads();

    const float* W = eW + (long)half * F2_ * C_;
    int cq = tid & 31, tg = tid >> 5;
    int c0 = cq * 4, t0 = tg * 5;
    u64 acc[5][2];
#pragma unroll
    for (int t = 0; t < 5; t++) { acc[t][0] = 0ull; acc[t][1] = 0ull; }

#pragma unroll 4
    for (int k = 0; k < F2_; k += 2) {
        ulonglong2 w0 = *(const ulonglong2*)(W + (long)k * C_ + c0);
        ulonglong2 w1 = *(const ulonglong2*)(W + (long)(k + 1) * C_ + c0);
#pragma unroll
        for (int t = 0; t < 5; t++) {
            ulonglong2 xd = *(const ulonglong2*)(fd2 + (t0 + t) * FD2_ + k);
            acc[t][0] = fma2(w0.x, xd.x, acc[t][0]);
            acc[t][1] = fma2(w0.y, xd.x, acc[t][1]);
            acc[t][0] = fma2(w1.x, xd.y, acc[t][0]);
            acc[t][1] = fma2(w1.y, xd.y, acc[t][1]);
        }
    }
    float4 bias = *(const float4*)(eb + half * C_ + c0);
#pragma unroll
    for (int t = 0; t < 5; t++) {
        float2 p0 = up2(acc[t][0]), p1 = up2(acc[t][1]);
        float4 o;
        o.x = p0.x + bias.x; o.y = p0.y + bias.y;
        o.z = p1.x + bias.z; o.w = p1.y + bias.w;
        *(float4*)(out + ((long)b * TK_ + half * K_ + t0 + t) * C_ + c0) = o;
    }
}

// ================= token mixing: LN over tokens + FFN 40->20->40 =================
__global__ __launch_bounds__(128)
void k_tokmix(float* __restrict__ x, const float* __restrict__ tg,
              const float* __restrict__ tbb, const float* __restrict__ W1,
              const float* __restrict__ b1, const float* __restrict__ W2,
              const float* __restrict__ b2, int mi)
{
    __shared__ float sW1[TK_ * HT_], sW2[HT_ * TK_];
    __shared__ float sb1[HT_], sb2[TK_], sg[TK_], sb[TK_];
    int tid = threadIdx.x, b = blockIdx.x;
    for (int i = tid; i < TK_ * HT_; i += 128) sW1[i] = W1[mi * TK_ * HT_ + i];
    for (int i = tid; i < HT_ * TK_; i += 128) sW2[i] = W2[mi * HT_ * TK_ + i];
    if (tid < HT_) sb1[tid] = b1[mi * HT_ + tid];
    if (tid < TK_) {
        sb2[tid] = b2[mi * TK_ + tid];
        sg[tid]  = tg[mi * TK_ + tid];
        sb[tid]  = tbb[mi * TK_ + tid];
    }
    __syncthreads();

    float* xb = x + (long)b * TK_ * C_ + tid;
    float xv[TK_];
#pragma unroll
    for (int t = 0; t < TK_; t++) xv[t] = xb[t * C_];
    float m = 0.0f;
#pragma unroll
    for (int t = 0; t < TK_; t++) m += xv[t];
    m *= (1.0f / TK_);
    float var = 0.0f;
#pragma unroll
    for (int t = 0; t < TK_; t++) { float d = xv[t] - m; var += d * d; }
    var *= (1.0f / TK_);
    float inv = rsqrtf(var + 1e-5f);
    float xn[TK_];
#pragma unroll
    for (int t = 0; t < TK_; t++) xn[t] = (xv[t] - m) * inv * sg[t] + sb[t];
    float g[HT_];
#pragma unroll
    for (int j = 0; j < HT_; j++) {
        float s = sb1[j];
#pragma unroll
        for (int t = 0; t < TK_; t++) s += xn[t] * sW1[t * HT_ + j];
        g[j] = gelu_f(s);
    }
#pragma unroll
    for (int t = 0; t < TK_; t++) {
        float o = sb2[t];
#pragma unroll
        for (int j = 0; j < HT_; j++) o += g[j] * sW2[j * TK_ + t];
        xb[t * C_] = xv[t] + o;
    }
}

// ================= channel mixing: LN + FFN 128->512->128 (f32x2, fused) =================
// 256 threads: ct = tid&15 -> cols ct*8..+7; rt = tid>>4 -> rows rt*4..+3. 64 rows/CTA.
#define CM_ROWS_ 64
#define XND_     130   /* u64 stride, even */
#define HDS_     130   /* u64 stride, even */
#define WSS_     132   /* float stride, 132*4 % 16 == 0 */
__global__ __launch_bounds__(256)
void k_chmix(float* __restrict__ X, const float* __restrict__ cg,
             const float* __restrict__ cb, const float* __restrict__ W1,
             const float* __restrict__ b1, const float* __restrict__ W2,
             const float* __restrict__ b2, int mi)
{
    extern __shared__ u64 dyn[];
    u64*   xnd = dyn;                        // [64][XND_] duplicated LN output
    u64*   hd  = xnd + CM_ROWS_ * XND_;      // [64][HDS_] duplicated hidden chunk
    float* wsf = (float*)(hd + CM_ROWS_ * HDS_);   // [128][WSS_]
    __shared__ float scg[C_], scb[C_], sbb1[HC_], sbb2[C_];
    int tid = threadIdx.x;
    for (int i = tid; i < C_; i += 256) {
        scg[i]  = cg[mi * C_ + i];
        scb[i]  = cb[mi * C_ + i];
        sbb2[i] = b2[mi * C_ + i];
    }
    for (int i = tid; i < HC_; i += 256) sbb1[i] = b1[mi * HC_ + i];

    long row0 = (long)blockIdx.x * CM_ROWS_;
    int warp = tid >> 5, lane = tid & 31;
    __syncthreads();

    // ---- LayerNorm over C for 64 rows (8 rows per warp), write duplicated ----
    for (int rr = 0; rr < 8; rr++) {
        int r = warp * 8 + rr;
        const float* xr = X + (row0 + r) * C_;
        float v0 = xr[lane], v1 = xr[lane + 32], v2 = xr[lane + 64], v3 = xr[lane + 96];
        float s = v0 + v1 + v2 + v3;
        for (int o = 16; o; o >>= 1) s += __shfl_xor_sync(0xffffffffu, s, o);
        float m = s * (1.0f / C_);
        float d0 = v0 - m, d1 = v1 - m, d2 = v2 - m, d3 = v3 - m;
        float q = d0 * d0 + d1 * d1 + d2 * d2 + d3 * d3;
        for (int o = 16; o; o >>= 1) q += __shfl_xor_sync(0xffffffffu, q, o);
        float inv = rsqrtf(q * (1.0f / C_) + 1e-5f);
        u64* xo = xnd + r * XND_;
        float a0 = d0 * inv * scg[lane]      + scb[lane];
        float a1 = d1 * inv * scg[lane + 32] + scb[lane + 32];
        float a2 = d2 * inv * scg[lane + 64] + scb[lane + 64];
        float a3 = d3 * inv * scg[lane + 96] + scb[lane + 96];
        xo[lane]      = pk2(a0, a0);
        xo[lane + 32] = pk2(a1, a1);
        xo[lane + 64] = pk2(a2, a2);
        xo[lane + 96] = pk2(a3, a3);
    }

    const float* W1p = W1 + (long)mi * C_ * HC_;
    const float* W2p = W2 + (long)mi * HC_ * C_;
    int ct = tid & 15, rt = tid >> 4;
    int c0 = ct * 8, r0 = rt * 4;

    u64 acc2[4][4];
#pragma unroll
    for (int r = 0; r < 4; r++)
#pragma unroll
        for (int p = 0; p < 4; p++) acc2[r][p] = 0ull;

    for (int nb = 0; nb < 4; nb++) {
        // stage W1 chunk [K=128][N=128]
        __syncthreads();
        for (int idx = tid; idx < 128 * 32; idx += 256) {
            int k = idx >> 5, j4 = (idx & 31) * 4;
            *(float4*)(wsf + k * WSS_ + j4) =
                *(const float4*)(W1p + (long)k * HC_ + nb * 128 + j4);
        }
        __syncthreads();

        // GEMM1: acc1 = xn @ W1chunk
        u64 acc1[4][4];
#pragma unroll
        for (int r = 0; r < 4; r++)
#pragma unroll
            for (int p = 0; p < 4; p++) acc1[r][p] = 0ull;
#pragma unroll 4
        for (int k = 0; k < 128; k += 2) {
            ulonglong2 wa  = *(const ulonglong2*)(wsf + k * WSS_ + c0);
            ulonglong2 wb  = *(const ulonglong2*)(wsf + k * WSS_ + c0 + 4);
            ulonglong2 wa1 = *(const ulonglong2*)(wsf + (k + 1) * WSS_ + c0);
            ulonglong2 wb1 = *(const ulonglong2*)(wsf + (k + 1) * WSS_ + c0 + 4);
#pragma unroll
            for (int r = 0; r < 4; r++) {
                ulonglong2 xd = *(const ulonglong2*)(xnd + (r0 + r) * XND_ + k);
                acc1[r][0] = fma2(wa.x,  xd.x, acc1[r][0]);
                acc1[r][1] = fma2(wa.y,  xd.x, acc1[r][1]);
                acc1[r][2] = fma2(wb.x,  xd.x, acc1[r][2]);
                acc1[r][3] = fma2(wb.y,  xd.x, acc1[r][3]);
                acc1[r][0] = fma2(wa1.x, xd.y, acc1[r][0]);
                acc1[r][1] = fma2(wa1.y, xd.y, acc1[r][1]);
                acc1[r][2] = fma2(wb1.x, xd.y, acc1[r][2]);
                acc1[r][3] = fma2(wb1.y, xd.y, acc1[r][3]);
            }
        }
        // bias + gelu, write duplicated hidden chunk
#pragma unroll
        for (int r = 0; r < 4; r++) {
            u64* hp = hd + (r0 + r) * HDS_ + c0;
#pragma unroll
            for (int p = 0; p < 4; p += 2) {
                float2 ga = up2(acc1[r][p]);
                float2 gb = up2(acc1[r][p + 1]);
                float h0 = gelu_f(ga.x + sbb1[nb * 128 + c0 + 2 * p]);
                float h1 = gelu_f(ga.y + sbb1[nb * 128 + c0 + 2 * p + 1]);
                float h2 = gelu_f(gb.x + sbb1[nb * 128 + c0 + 2 * p + 2]);
                float h3 = gelu_f(gb.y + sbb1[nb * 128 + c0 + 2 * p + 3]);
                ulonglong2 st;
                st.x = pk2(h0, h0); st.y = pk2(h1, h1);
                *(ulonglong2*)(hp + 2 * p) = st;
                st.x = pk2(h2, h2); st.y = pk2(h3, h3);
                *(ulonglong2*)(hp + 2 * p + 2) = st;
            }
        }
        __syncthreads();
        // stage W2 chunk [K=128][N=128]
        for (int idx = tid; idx < 128 * 32; idx += 256) {
            int k = idx >> 5, j4 = (idx & 31) * 4;
            *(float4*)(wsf + k * WSS_ + j4) =
                *(const float4*)(W2p + (long)(nb * 128 + k) * C_ + j4);
        }
        __syncthreads();
        // GEMM2 partial: acc2 += h_chunk @ W2chunk
#pragma unroll 4
        for (int k = 0; k < 128; k += 2) {
            ulonglong2 wa  = *(const ulonglong2*)(wsf + k * WSS_ + c0);
            ulonglong2 wb  = *(const ulonglong2*)(wsf + k * WSS_ + c0 + 4);
            ulonglong2 wa1 = *(const ulonglong2*)(wsf + (k + 1) * WSS_ + c0);
            ulonglong2 wb1 = *(const ulonglong2*)(wsf + (k + 1) * WSS_ + c0 + 4);
#pragma unroll
            for (int r = 0; r < 4; r++) {
                ulonglong2 xd = *(const ulonglong2*)(hd + (r0 + r) * HDS_ + k);
                acc2[r][0] = fma2(wa.x,  xd.x, acc2[r][0]);
                acc2[r][1] = fma2(wa.y,  xd.x, acc2[r][1]);
                acc2[r][2] = fma2(wb.x,  xd.x, acc2[r][2]);
                acc2[r][3] = fma2(wb.y,  xd.x, acc2[r][3]);
                acc2[r][0] = fma2(wa1.x, xd.y, acc2[r][0]);
                acc2[r][1] = fma2(wa1.y, xd.y, acc2[r][1]);
                acc2[r][2] = fma2(wb1.x, xd.y, acc2[r][2]);
                acc2[r][3] = fma2(wb1.y, xd.y, acc2[r][3]);
            }
        }
    }

    // residual + bias, in place
#pragma unroll
    for (int r = 0; r < 4; r++) {
        long row = row0 + r0 + r;
        float4 xa = *(const float4*)(X + row * C_ + c0);
        float4 xb = *(const float4*)(X + row * C_ + c0 + 4);
        float2 p0 = up2(acc2[r][0]), p1 = up2(acc2[r][1]);
        float2 p2 = up2(acc2[r][2]), p3 = up2(acc2[r][3]);
        float4 oa, ob;
        oa.x = xa.x + p0.x + sbb2[c0 + 0]; oa.y = xa.y + p0.y + sbb2[c0 + 1];
        oa.z = xa.z + p1.x + sbb2[c0 + 2]; oa.w = xa.w + p1.y + sbb2[c0 + 3];
        ob.x = xb.x + p2.x + sbb2[c0 + 4]; ob.y = xb.y + p2.y + sbb2[c0 + 5];
        ob.z = xb.z + p3.x + sbb2[c0 + 6]; ob.w = xb.w + p3.y + sbb2[c0 + 7];
        *(float4*)(X + row * C_ + c0)     = oa;
        *(float4*)(X + row * C_ + c0 + 4) = ob;
    }
}

// ================= mean over tokens + pcc-softmax combine =================
__global__ __launch_bounds__(128)
void k_final(const float* __restrict__ t1, const float* __restrict__ t2,
             const float* __restrict__ pcc1, const float* __restrict__ pcc2,
             float* __restrict__ out)
{
    int b = blockIdx.x, c = threadIdx.x;
    const float* p1 = t1 + (long)b * TK_ * C_ + c;
    const float* p2 = t2 + (long)b * TK_ * C_ + c;
    float s1 = 0.0f, s2 = 0.0f;
#pragma unroll
    for (int t = 0; t < TK_; t++) { s1 += p1[t * C_]; s2 += p2[t * C_]; }
    s1 *= (1.0f / TK_);
    s2 *= (1.0f / TK_);
    float a = pcc1[b], bb = pcc2[b];
    float m = fmaxf(a, bb);
    float e1 = expf(a - m), e2 = expf(bb - m);
    float w1 = e1 / (e1 + e2);
    out[(long)b * C_ + c] = w1 * s1 + (1.0f - w1) * s2;
}

// ================= launch =================
extern "C" void kernel_launch(void* const* d_in, const int* in_sizes, int n_in,
                              void* d_out, int out_size)
{
    const float* edge_table = (const float*)d_in[0];
    const int*   src_eids   = (const int*)d_in[1];
    const int*   dst_eids   = (const int*)d_in[2];
    const int*   src2_e1    = (const int*)d_in[3];
    const int*   src2_e2    = (const int*)d_in[4];
    const int*   dst2_e1    = (const int*)d_in[5];
    const int*   dst2_e2    = (const int*)d_in[6];
    const float* dt_src     = (const float*)d_in[7];
    const float* dt_dst     = (const float*)d_in[8];
    const float* dt2_src    = (const float*)d_in[9];
    const float* dt2_dst    = (const float*)d_in[10];
    const float* pcc1       = (const float*)d_in[11];
    const float* pcc2       = (const float*)d_in[12];
    const float* time_w     = (const float*)d_in[13];
    const float* time_b     = (const float*)d_in[14];
    const float* proj_W     = (const float*)d_in[15];
    const float* proj_b     = (const float*)d_in[16];
    const float* eproj_W    = (const float*)d_in[17];
    const float* eproj_b    = (const float*)d_in[18];
    const float* tln_g      = (const float*)d_in[19];
    const float* tln_b      = (const float*)d_in[20];
    const float* tW1        = (const float*)d_in[21];
    const float* tb1        = (const float*)d_in[22];
    const float* tW2        = (const float*)d_in[23];
    const float* tb2        = (const float*)d_in[24];
    const float* cln_g      = (const float*)d_in[25];
    const float* cln_b      = (const float*)d_in[26];
    const float* cW1        = (const float*)d_in[27];
    const float* cb1        = (const float*)d_in[28];
    const float* cW2        = (const float*)d_in[29];
    const float* cb2        = (const float*)d_in[30];
    float* out = (float*)d_out;

    float* tok1; cudaGetSymbolAddress((void**)&tok1, g_tok1);
    float* tok2; cudaGetSymbolAddress((void**)&tok2, g_tok2);

    const int smem_b1 = TK_ * FD1_ * (int)sizeof(u64);                 // 73600
    const int smem_b2 = K_ * FD2_ * (int)sizeof(u64);                  // 77760
    const int smem_ch = (CM_ROWS_ * XND_ + CM_ROWS_ * HDS_) * (int)sizeof(u64)
                      + 128 * WSS_ * (int)sizeof(float);               // 200704
    cudaFuncSetAttribute(k_build1, cudaFuncAttributeMaxDynamicSharedMemorySize, smem_b1);
    cudaFuncSetAttribute(k_build2, cudaFuncAttributeMaxDynamicSharedMemorySize, smem_b2);
    cudaFuncSetAttribute(k_chmix,  cudaFuncAttributeMaxDynamicSharedMemorySize, smem_ch);

    const int chgrid = (B_ * TK_) / CM_ROWS_;   // 1280

    // ---- stack 1: one-hop ----
    k_build1<<<B_, 128, smem_b1>>>(edge_table, src_eids, dst_eids, dt_src, dt_dst,
                                   time_w, time_b, proj_W, proj_b, tok1);
    for (int i = 0; i < 2; i++) {
        k_tokmix<<<B_, 128>>>(tok1, tln_g, tln_b, tW1, tb1, tW2, tb2, i);
        k_chmix<<<chgrid, 256, smem_ch>>>(tok1, cln_g, cln_b, cW1, cb1, cW2, cb2, i);
    }

    // ---- stack 2: two-hop ----
    k_build2<<<2 * B_, 128, smem_b2>>>(edge_table, src_eids, dst_eids,
                                       src2_e1, src2_e2, dst2_e1, dst2_e2,
                                       dt2_src, dt2_dst, time_w, time_b,
                                       eproj_W, eproj_b, tok2);
    for (int i = 0; i < 2; i++) {
        k_tokmix<<<B_, 128>>>(tok2, tln_g, tln_b, tW1, tb1, tW2, tb2, 2 + i);
        k_chmix<<<chgrid, 256, smem_ch>>>(tok2, cln_g, cln_b, cW1, cb1, cW2, cb2, 2 + i);
    }

    k_final<<<B_, 128>>>(tok1, tok2, pcc1, pcc2, out);
}

// round 6
// speedup vs baseline: 1.6961x; 1.6961x over previous
#include <cuda_runtime.h>
#include <cuda_bf16.h>
#include <math.h>

#define B_    2048
#define K_    20
#define TK_   40
#define D_    128
#define T_    100
#define C_    128
#define HT_   20
#define HC_   512
#define F1_   228   /* D+T  */
#define F2_   484   /* 3D+T */

typedef unsigned long long u64;
typedef unsigned int u32;

// ---------------- scratch (no allocations allowed) ----------------
__device__ float g_tok1[B_ * TK_ * C_];
__device__ float g_tok2[B_ * TK_ * C_];
// B fragments, mma.sync per-lane layout:
// tile64 = ((mi*8 + t)*2 + hl), t: 0-3 W1 groups, 4-7 W2 chunks, hl: 0=hi,1=lo
// offset = (((tile64*8 + kt)*16 + nt)*32 + lane)*2   (u32 pairs {b0,b1})
__device__ u32 g_wfrag[64 * 8 * 16 * 32 * 2];

__device__ __forceinline__ float gelu_f(float x) {
    return 0.5f * x * (1.0f + erff(x * 0.70710678118654752f));
}
__device__ __forceinline__ u32 smem_u32(const void* p) {
    u32 a;
    asm("{ .reg .u64 t; cvta.to.shared.u64 t, %1; cvt.u32.u64 %0, t; }" : "=r"(a) : "l"(p));
    return a;
}
__device__ __forceinline__ void ldm4(u32* r, u32 addr) {
    asm volatile("ldmatrix.sync.aligned.m8n8.x4.shared.b16 {%0,%1,%2,%3}, [%4];"
                 : "=r"(r[0]), "=r"(r[1]), "=r"(r[2]), "=r"(r[3]) : "r"(addr));
}
__device__ __forceinline__ void mma_bf16(float* c, const u32* a, u32 b0, u32 b1) {
    asm volatile("mma.sync.aligned.m16n8k16.row.col.f32.bf16.bf16.f32 "
                 "{%0,%1,%2,%3}, {%4,%5,%6,%7}, {%8,%9}, {%0,%1,%2,%3};"
                 : "+f"(c[0]), "+f"(c[1]), "+f"(c[2]), "+f"(c[3])
                 : "r"(a[0]), "r"(a[1]), "r"(a[2]), "r"(a[3]), "r"(b0), "r"(b1));
}
__device__ __forceinline__ unsigned short bf16b(float v) {
    __nv_bfloat16 h = __float2bfloat16(v);
    return *(unsigned short*)&h;
}
__device__ __forceinline__ float bf16f(unsigned short s) {
    __nv_bfloat16 h = *(__nv_bfloat16*)&s;
    return __bfloat162float(h);
}

// ================= weight prep: fp32 -> bf16 hi/lo B-fragments =================
__global__ __launch_bounds__(256)
void k_prep_frag(const float* __restrict__ cW1, const float* __restrict__ cW2)
{
    int idx = blockIdx.x * 256 + threadIdx.x;   // 0 .. 262143
    int lane = idx & 31;
    int rest = idx >> 5;
    int nt = rest & 15;
    int kt = (rest >> 4) & 7;
    int tile64 = idx >> 12;                     // 0..63
    int hl = tile64 & 1;
    int t  = (tile64 >> 1) & 7;
    int mi = tile64 >> 4;
    int gid = lane >> 2, tig = lane & 3;
    int n_local = nt * 8 + gid;

    u32 outw[2];
#pragma unroll
    for (int h = 0; h < 2; h++) {
        int k0 = kt * 16 + tig * 2 + h * 8;
        float v0, v1;
        if (t < 4) {  // W1: [C_ (k)][HC_ (n)], group t
            v0 = cW1[mi * (C_ * HC_) + k0 * HC_ + t * 128 + n_local];
            v1 = cW1[mi * (C_ * HC_) + (k0 + 1) * HC_ + t * 128 + n_local];
        } else {      // W2: [HC_ (k)][C_ (n)], chunk t-4
            v0 = cW2[mi * (HC_ * C_) + ((t - 4) * 128 + k0) * C_ + n_local];
            v1 = cW2[mi * (HC_ * C_) + ((t - 4) * 128 + k0 + 1) * C_ + n_local];
        }
        unsigned short s0, s1;
        if (hl == 0) { s0 = bf16b(v0); s1 = bf16b(v1); }
        else {
            s0 = bf16b(v0 - bf16f(bf16b(v0)));
            s1 = bf16b(v1 - bf16f(bf16b(v1)));
        }
        outw[h] = ((u32)s1 << 16) | (u32)s0;
    }
    u32* dst = g_wfrag + (u64)idx * 2;
    dst[0] = outw[0];
    dst[1] = outw[1];
}

// ================= channel mixing: LN + FFN via mma.sync bf16 hi/lo =================
// CTA: 256 threads, 8 warps; warp w owns rows w*16..w*16+15 of a 128-row tile.
#define AS_ 136                 /* bf16 row stride: 272B, 16B-aligned */
#define DSM_CH_ (4 * 128 * AS_ * 2)

__global__ __launch_bounds__(256)
void k_chmix_mma(float* __restrict__ X, const float* __restrict__ cg,
                 const float* __restrict__ cb, const float* __restrict__ b1,
                 const float* __restrict__ b2, int mi)
{
    extern __shared__ __nv_bfloat16 sm_bf[];
    __nv_bfloat16* a_hi = sm_bf;
    __nv_bfloat16* a_lo = a_hi + 128 * AS_;
    __nv_bfloat16* h_hi = a_lo + 128 * AS_;
    __nv_bfloat16* h_lo = h_hi + 128 * AS_;
    __shared__ float scg[C_], scb[C_], sbb1[HC_], sbb2[C_];

    int tid = threadIdx.x, wid = tid >> 5, lane = tid & 31;
    long row0 = (long)blockIdx.x * 128;

    for (int i = tid; i < C_; i += 256) {
        scg[i]  = cg[mi * C_ + i];
        scb[i]  = cb[mi * C_ + i];
        sbb2[i] = b2[mi * C_ + i];
    }
    for (int i = tid; i < HC_; i += 256) sbb1[i] = b1[mi * HC_ + i];
    __syncthreads();   // only sync in the kernel: each warp owns its rows after this

    // ---- LayerNorm over C, 16 rows per warp, write bf16 hi/lo (row-major) ----
    for (int rr = 0; rr < 16; rr++) {
        int r = wid * 16 + rr;
        const float* xr = X + (row0 + r) * C_;
        float v0 = xr[lane], v1 = xr[lane + 32], v2 = xr[lane + 64], v3 = xr[lane + 96];
        float s = v0 + v1 + v2 + v3;
        for (int o = 16; o; o >>= 1) s += __shfl_xor_sync(0xffffffffu, s, o);
        float m = s * (1.0f / C_);
        float e0 = v0 - m, e1 = v1 - m, e2 = v2 - m, e3 = v3 - m;
        float q = e0 * e0 + e1 * e1 + e2 * e2 + e3 * e3;
        for (int o = 16; o; o >>= 1) q += __shfl_xor_sync(0xffffffffu, q, o);
        float inv = rsqrtf(q * (1.0f / C_) + 1e-5f);
        float av[4] = { e0 * inv * scg[lane]      + scb[lane],
                        e1 * inv * scg[lane + 32] + scb[lane + 32],
                        e2 * inv * scg[lane + 64] + scb[lane + 64],
                        e3 * inv * scg[lane + 96] + scb[lane + 96] };
#pragma unroll
        for (int p = 0; p < 4; p++) {
            int c = lane + p * 32;
            unsigned short hi = bf16b(av[p]);
            unsigned short lo = bf16b(av[p] - bf16f(hi));
            a_hi[r * AS_ + c] = *(__nv_bfloat16*)&hi;
            a_lo[r * AS_ + c] = *(__nv_bfloat16*)&lo;
        }
    }

    int gid = lane >> 2, tig = lane & 3;
    int seg = lane >> 3, rin = lane & 7;
    int r0 = wid * 16;
    int arow = r0 + (seg & 1) * 8 + rin;    // ldmatrix row for this thread
    int acol = (seg >> 1) * 8;              // ldmatrix col offset

    float acc2[16][4];
#pragma unroll
    for (int nt = 0; nt < 16; nt++)
#pragma unroll
        for (int i = 0; i < 4; i++) acc2[nt][i] = 0.0f;

    for (int nb = 0; nb < 4; nb++) {
        const u32* wf1h = g_wfrag + (u64)((mi * 8 + nb) * 2 + 0) * 8192;
        const u32* wf1l = wf1h + 8192;

        float acc1[16][4];
#pragma unroll
        for (int nt = 0; nt < 16; nt++)
#pragma unroll
            for (int i = 0; i < 4; i++) acc1[nt][i] = 0.0f;

        // GEMM1: A(128x128) @ W1group -> H chunk
        for (int kt = 0; kt < 8; kt++) {
            u32 ah[4], al[4];
            ldm4(ah, smem_u32(a_hi + arow * AS_ + kt * 16 + acol));
            ldm4(al, smem_u32(a_lo + arow * AS_ + kt * 16 + acol));
#pragma unroll
            for (int nt = 0; nt < 16; nt++) {
                int fo = ((kt * 16 + nt) * 32 + lane) * 2;
                uint2 bh = *(const uint2*)(wf1h + fo);
                uint2 bl = *(const uint2*)(wf1l + fo);
                mma_bf16(acc1[nt], ah, bh.x, bh.y);
                mma_bf16(acc1[nt], ah, bl.x, bl.y);
                mma_bf16(acc1[nt], al, bh.x, bh.y);
            }
        }

        // bias + gelu -> h tiles (warp-private rows; no sync needed)
#pragma unroll
        for (int nt = 0; nt < 16; nt++) {
#pragma unroll
            for (int i2 = 0; i2 < 2; i2++) {
                int row = r0 + gid + i2 * 8;
                int col = nt * 8 + tig * 2;
                float g0 = gelu_f(acc1[nt][i2 * 2 + 0] + sbb1[nb * 128 + col]);
                float g1 = gelu_f(acc1[nt][i2 * 2 + 1] + sbb1[nb * 128 + col + 1]);
                unsigned short h0 = bf16b(g0), h1 = bf16b(g1);
                unsigned short l0 = bf16b(g0 - bf16f(h0)), l1 = bf16b(g1 - bf16f(h1));
                *(u32*)(h_hi + row * AS_ + col) = ((u32)h1 << 16) | h0;
                *(u32*)(h_lo + row * AS_ + col) = ((u32)l1 << 16) | l0;
            }
        }

        // GEMM2 partial: H chunk @ W2chunk -> acc2
        const u32* wf2h = g_wfrag + (u64)((mi * 8 + 4 + nb) * 2 + 0) * 8192;
        const u32* wf2l = wf2h + 8192;
        for (int kt = 0; kt < 8; kt++) {
            u32 ah[4], al[4];
            ldm4(ah, smem_u32(h_hi + arow * AS_ + kt * 16 + acol));
            ldm4(al, smem_u32(h_lo + arow * AS_ + kt * 16 + acol));
#pragma unroll
            for (int nt = 0; nt < 16; nt++) {
                int fo = ((kt * 16 + nt) * 32 + lane) * 2;
                uint2 bh = *(const uint2*)(wf2h + fo);
                uint2 bl = *(const uint2*)(wf2l + fo);
                mma_bf16(acc2[nt], ah, bh.x, bh.y);
                mma_bf16(acc2[nt], ah, bl.x, bl.y);
                mma_bf16(acc2[nt], al, bh.x, bh.y);
            }
        }
    }

    // residual + bias2 writeback (fragment layout, float2 stores)
#pragma unroll
    for (int nt = 0; nt < 16; nt++) {
#pragma unroll
        for (int i2 = 0; i2 < 2; i2++) {
            int row = r0 + gid + i2 * 8;
            int col = nt * 8 + tig * 2;
            float* xp = X + (row0 + row) * C_ + col;
            float2 xv = *(float2*)xp;
            xv.x += acc2[nt][i2 * 2 + 0] + sbb2[col];
            xv.y += acc2[nt][i2 * 2 + 1] + sbb2[col + 1];
            *(float2*)xp = xv;
        }
    }
}

// ================= one-hop build (R1 scalar, known good) =================
__global__ __launch_bounds__(128)
void k_build1(const float* __restrict__ et, const int* __restrict__ se,
              const int* __restrict__ de, const float* __restrict__ dts,
              const float* __restrict__ dtd, const float* __restrict__ tw,
              const float* __restrict__ tb, const float* __restrict__ pW,
              const float* __restrict__ pb, float* __restrict__ out)
{
    __shared__ float feat[TK_ * F1_];
    __shared__ int   s_eid[TK_];
    __shared__ float s_dt[TK_];
    int b = blockIdx.x, tid = threadIdx.x;
    if (tid < TK_) {
        int half = tid / K_, k = tid - half * K_;
        int eid = half ? de[b * K_ + k] : se[b * K_ + k];
        s_eid[tid] = eid;
        s_dt[tid]  = half ? dtd[b * K_ + k] : dts[b * K_ + k];
    }
    __syncthreads();
    for (int idx = tid; idx < TK_ * F1_; idx += 128) {
        int t = idx / F1_, f = idx - t * F1_;
        float v;
        if (f < D_) v = et[(long)s_eid[t] * D_ + f];
        else {
            int j = f - D_;
            v = (s_eid[t] == 0) ? 0.0f : cosf(s_dt[t] * tw[j] + tb[j]);
        }
        feat[idx] = v;
    }
    __syncthreads();
    float acc[TK_];
#pragma unroll
    for (int t = 0; t < TK_; t++) acc[t] = 0.0f;
    int c = tid;
    for (int k = 0; k < F1_; k++) {
        float w = pW[k * C_ + c];
#pragma unroll
        for (int t = 0; t < TK_; t++) acc[t] += feat[t * F1_ + k] * w;
    }
    float bias = pb[c];
    float* ob = out + (long)b * TK_ * C_ + c;
#pragma unroll
    for (int t = 0; t < TK_; t++) ob[t * C_] = acc[t] + bias;
}

// ================= two-hop build (R1 scalar, known good) =================
__global__ __launch_bounds__(128)
void k_build2(const float* __restrict__ et, const int* __restrict__ se,
              const int* __restrict__ de, const int* __restrict__ s2a,
              const int* __restrict__ s2b, const int* __restrict__ d2a,
              const int* __restrict__ d2b, const float* __restrict__ dt2s,
              const float* __restrict__ dt2d, const float* __restrict__ tw,
              const float* __restrict__ tb, const float* __restrict__ eW,
              const float* __restrict__ eb, float* __restrict__ out)
{
    __shared__ float feat[K_ * F2_];
    __shared__ int s1[K_], s2[K_], s3[K_];
    __shared__ float sdt[K_];
    int bh = blockIdx.x;
    int b = bh >> 1, half = bh & 1, tid = threadIdx.x;
    if (tid < K_) {
        s1[tid] = half ? d2a[b * K_ + tid] : s2a[b * K_ + tid];
        s2[tid] = half ? d2b[b * K_ + tid] : s2b[b * K_ + tid];
        s3[tid] = half ? de[b * K_ + tid]  : se[b * K_ + tid];
        sdt[tid] = half ? dt2d[b * K_ + tid] : dt2s[b * K_ + tid];
    }
    __syncthreads();
    for (int idx = tid; idx < K_ * F2_; idx += 128) {
        int t = idx / F2_, f = idx - t * F2_;
        float v;
        if (f < D_)              v = et[(long)s1[t] * D_ + f];
        else if (f < 2 * D_)     v = et[(long)s2[t] * D_ + (f - D_)];
        else if (f < 3 * D_)     v = et[(long)s3[t] * D_ + (f - 2 * D_)];
        else {
            int j = f - 3 * D_;
            v = (s1[t] == 0) ? 0.0f : cosf(sdt[t] * tw[j] + tb[j]);
        }
        feat[idx] = v;
    }
    __syncthreads();
    const float* W = eW + (long)half * F2_ * C_;
    float acc[K_];
#pragma unroll
    for (int t = 0; t < K_; t++) acc[t] = 0.0f;
    int c = tid;
    for (int k = 0; k < F2_; k++) {
        float w = W[k * C_ + c];
#pragma unroll
        for (int t = 0; t < K_; t++) acc[t] += feat[t * F2_ + k] * w;
    }
    float bias = eb[half * C_ + c];
    float* ob = out + ((long)b * TK_ + half * K_) * C_ + c;
#pragma unroll
    for (int t = 0; t < K_; t++) ob[t * C_] = acc[t] + bias;
}

// ================= token mixing (R1, known good) =================
__global__ __launch_bounds__(128)
void k_tokmix(float* __restrict__ x, const float* __restrict__ tg,
              const float* __restrict__ tbb, const float* __restrict__ W1,
              const float* __restrict__ b1, const float* __restrict__ W2,
              const float* __restrict__ b2, int mi)
{
    __shared__ float sW1[TK_ * HT_], sW2[HT_ * TK_];
    __shared__ float sb1[HT_], sb2[TK_], sg[TK_], sb[TK_];
    int tid = threadIdx.x, b = blockIdx.x;
    for (int i = tid; i < TK_ * HT_; i += 128) sW1[i] = W1[mi * TK_ * HT_ + i];
    for (int i = tid; i < HT_ * TK_; i += 128) sW2[i] = W2[mi * HT_ * TK_ + i];
    if (tid < HT_) sb1[tid] = b1[mi * HT_ + tid];
    if (tid < TK_) {
        sb2[tid] = b2[mi * TK_ + tid];
        sg[tid]  = tg[mi * TK_ + tid];
        sb[tid]  = tbb[mi * TK_ + tid];
    }
    __syncthreads();

    float* xb = x + (long)b * TK_ * C_ + tid;
    float xv[TK_];
#pragma unroll
    for (int t = 0; t < TK_; t++) xv[t] = xb[t * C_];
    float m = 0.0f;
#pragma unroll
    for (int t = 0; t < TK_; t++) m += xv[t];
    m *= (1.0f / TK_);
    float var = 0.0f;
#pragma unroll
    for (int t = 0; t < TK_; t++) { float d = xv[t] - m; var += d * d; }
    var *= (1.0f / TK_);
    float inv = rsqrtf(var + 1e-5f);
    float xn[TK_];
#pragma unroll
    for (int t = 0; t < TK_; t++) xn[t] = (xv[t] - m) * inv * sg[t] + sb[t];
    float g[HT_];
#pragma unroll
    for (int j = 0; j < HT_; j++) {
        float s = sb1[j];
#pragma unroll
        for (int t = 0; t < TK_; t++) s += xn[t] * sW1[t * HT_ + j];
        g[j] = gelu_f(s);
    }
#pragma unroll
    for (int t = 0; t < TK_; t++) {
        float o = sb2[t];
#pragma unroll
        for (int j = 0; j < HT_; j++) o += g[j] * sW2[j * TK_ + t];
        xb[t * C_] = xv[t] + o;
    }
}

// ================= mean + pcc-softmax combine (R1) =================
__global__ __launch_bounds__(128)
void k_final(const float* __restrict__ t1, const float* __restrict__ t2,
             const float* __restrict__ pcc1, const float* __restrict__ pcc2,
             float* __restrict__ out)
{
    int b = blockIdx.x, c = threadIdx.x;
    const float* p1 = t1 + (long)b * TK_ * C_ + c;
    const float* p2 = t2 + (long)b * TK_ * C_ + c;
    float s1 = 0.0f, s2 = 0.0f;
#pragma unroll
    for (int t = 0; t < TK_; t++) { s1 += p1[t * C_]; s2 += p2[t * C_]; }
    s1 *= (1.0f / TK_);
    s2 *= (1.0f / TK_);
    float a = pcc1[b], bb = pcc2[b];
    float m = fmaxf(a, bb);
    float e1 = expf(a - m), e2 = expf(bb - m);
    float w1 = e1 / (e1 + e2);
    out[(long)b * C_ + c] = w1 * s1 + (1.0f - w1) * s2;
}

// ================= launch =================
extern "C" void kernel_launch(void* const* d_in, const int* in_sizes, int n_in,
                              void* d_out, int out_size)
{
    const float* edge_table = (const float*)d_in[0];
    const int*   src_eids   = (const int*)d_in[1];
    const int*   dst_eids   = (const int*)d_in[2];
    const int*   src2_e1    = (const int*)d_in[3];
    const int*   src2_e2    = (const int*)d_in[4];
    const int*   dst2_e1    = (const int*)d_in[5];
    const int*   dst2_e2    = (const int*)d_in[6];
    const float* dt_src     = (const float*)d_in[7];
    const float* dt_dst     = (const float*)d_in[8];
    const float* dt2_src    = (const float*)d_in[9];
    const float* dt2_dst    = (const float*)d_in[10];
    const float* pcc1       = (const float*)d_in[11];
    const float* pcc2       = (const float*)d_in[12];
    const float* time_w     = (const float*)d_in[13];
    const float* time_b     = (const float*)d_in[14];
    const float* proj_W     = (const float*)d_in[15];
    const float* proj_b     = (const float*)d_in[16];
    const float* eproj_W    = (const float*)d_in[17];
    const float* eproj_b    = (const float*)d_in[18];
    const float* tln_g      = (const float*)d_in[19];
    const float* tln_b      = (const float*)d_in[20];
    const float* tW1        = (const float*)d_in[21];
    const float* tb1        = (const float*)d_in[22];
    const float* tW2        = (const float*)d_in[23];
    const float* tb2        = (const float*)d_in[24];
    const float* cln_g      = (const float*)d_in[25];
    const float* cln_b      = (const float*)d_in[26];
    const float* cW1        = (const float*)d_in[27];
    const float* cb1        = (const float*)d_in[28];
    const float* cW2        = (const float*)d_in[29];
    const float* cb2        = (const float*)d_in[30];
    float* out = (float*)d_out;

    float* tok1; cudaGetSymbolAddress((void**)&tok1, g_tok1);
    float* tok2; cudaGetSymbolAddress((void**)&tok2, g_tok2);

    cudaFuncSetAttribute(k_chmix_mma, cudaFuncAttributeMaxDynamicSharedMemorySize, DSM_CH_);

    const int chgrid = (B_ * TK_) / 128;   // 640

    // prep bf16 hi/lo B-fragments (inside graph; deterministic)
    k_prep_frag<<<1024, 256>>>(cW1, cW2);

    // ---- stack 1: one-hop ----
    k_build1<<<B_, 128>>>(edge_table, src_eids, dst_eids, dt_src, dt_dst,
                          time_w, time_b, proj_W, proj_b, tok1);
    for (int i = 0; i < 2; i++) {
        k_tokmix<<<B_, 128>>>(tok1, tln_g, tln_b, tW1, tb1, tW2, tb2, i);
        k_chmix_mma<<<chgrid, 256, DSM_CH_>>>(tok1, cln_g, cln_b, cb1, cb2, i);
    }

    // ---- stack 2: two-hop ----
    k_build2<<<2 * B_, 128>>>(edge_table, src_eids, dst_eids,
                              src2_e1, src2_e2, dst2_e1, dst2_e2,
                              dt2_src, dt2_dst, time_w, time_b,
                              eproj_W, eproj_b, tok2);
    for (int i = 0; i < 2; i++) {
        k_tokmix<<<B_, 128>>>(tok2, tln_g, tln_b, tW1, tb1, tW2, tb2, 2 + i);
        k_chmix_mma<<<chgrid, 256, DSM_CH_>>>(tok2, cln_g, cln_b, cb1, cb2, 2 + i);
    }

    k_final<<<B_, 128>>>(tok1, tok2, pcc1, pcc2, out);
}